// round 7
// baseline (speedup 1.0000x reference)
#include <cuda_runtime.h>

#define TPB 256
#define NF 10
#define EDIM 60
#define NC 64
#define DKDIM 5
#define INV_SQRT5 0.44721359549995793f

// Packed f32x2 FMA — ptxas never auto-fuses this from C++; PTX-only (sm_100+).
#define FMA2(d, a, b, c) \
    asm("fma.rn.f32x2 %0, %1, %2, %3;" : "=l"(d) : "l"(a), "l"(b), "l"(c))
#define PACK2(d, lo, hi) \
    asm("mov.b64 %0, {%1, %2};" : "=l"(d) : "f"(lo), "f"(hi))

__device__ float g_K[NC * DKDIM];  // K = posenc(centroids) @ Wk^T, precomputed

// ---------------------------------------------------------------------------
// Tiny kernel: K[c, k] = sum_e posenc(centroid_c)[e] * Wk[k, e]
// ---------------------------------------------------------------------------
__global__ void precompute_K_kernel(const float* __restrict__ Wk,
                                    const float* __restrict__ centroids) {
    int c = threadIdx.x;
    if (c >= NC) return;
    float x0 = centroids[c * 3 + 0];
    float x1 = centroids[c * 3 + 1];
    float x2 = centroids[c * 3 + 2];
    float enc[EDIM];
#pragma unroll
    for (int l = 0; l < NF; l++) {
        float f = (float)(1u << l);
        float s, co;
        sincosf(x0 * f, &s, &co); enc[l * 6 + 0] = s; enc[l * 6 + 3] = co;
        sincosf(x1 * f, &s, &co); enc[l * 6 + 1] = s; enc[l * 6 + 4] = co;
        sincosf(x2 * f, &s, &co); enc[l * 6 + 2] = s; enc[l * 6 + 5] = co;
    }
#pragma unroll
    for (int k = 0; k < DKDIM; k++) {
        float a = 0.f;
#pragma unroll
        for (int e = 0; e < EDIM; e++) a += enc[e] * Wk[k * EDIM + e];
        g_K[c * DKDIM + k] = a;
    }
}

// ---------------------------------------------------------------------------
// Main kernel: one thread per point.
//   enc (60) in regs; LM (192x60 = 46 KB) in smem, broadcast-read;
//   softmax fused unnormalized (divide by Z at the end) so the c-loop stays
//   rolled and no 64-entry register array is needed;
//   inner reduction uses packed fma.rn.f32x2 (2 FMAs/lane/instr).
// ---------------------------------------------------------------------------
__global__ __launch_bounds__(TPB) void csa_kernel(
    const float* __restrict__ X,
    const int*   __restrict__ cids,
    const float* __restrict__ LM,
    const float* __restrict__ Wq,
    const float* __restrict__ Wv,
    float* __restrict__ d_out,
    int N, int mode)   // mode 3: write [out | kmeans | attention]; mode 1: out only
{
    __shared__ __align__(16) float sLM[192 * EDIM];   // 46080 B
    __shared__ float sK[NC * DKDIM];
    __shared__ float sWq[DKDIM * EDIM];
    __shared__ float sWv[9];

    {
        const float4* src = (const float4*)LM;
        float4* dst = (float4*)sLM;
        for (int i = threadIdx.x; i < 192 * EDIM / 4; i += TPB) dst[i] = src[i];
        for (int i = threadIdx.x; i < NC * DKDIM; i += TPB) sK[i] = g_K[i];
        for (int i = threadIdx.x; i < DKDIM * EDIM; i += TPB) sWq[i] = Wq[i];
        if (threadIdx.x < 9) sWv[threadIdx.x] = Wv[threadIdx.x];
    }
    __syncthreads();

    int idx = blockIdx.x * TPB + threadIdx.x;
    if (idx >= N) return;

    float x0 = X[3 * idx + 0];
    float x1 = X[3 * idx + 1];
    float x2 = X[3 * idx + 2];

    // NeRF posenc: enc[l*6 + s*3 + d], s=0 sin, s=1 cos
    float enc[EDIM];
#pragma unroll
    for (int l = 0; l < NF; l++) {
        float f = (float)(1u << l);
        float s, co;
        sincosf(x0 * f, &s, &co); enc[l * 6 + 0] = s; enc[l * 6 + 3] = co;
        sincosf(x1 * f, &s, &co); enc[l * 6 + 1] = s; enc[l * 6 + 4] = co;
        sincosf(x2 * f, &s, &co); enc[l * 6 + 2] = s; enc[l * 6 + 5] = co;
    }

    // Q = enc @ Wq^T   [5]
    float q0 = 0.f, q1 = 0.f, q2 = 0.f, q3 = 0.f, q4 = 0.f;
#pragma unroll
    for (int e = 0; e < EDIM; e++) {
        float ev = enc[e];
        q0 += ev * sWq[0 * EDIM + e];
        q1 += ev * sWq[1 * EDIM + e];
        q2 += ev * sWq[2 * EDIM + e];
        q3 += ev * sWq[3 * EDIM + e];
        q4 += ev * sWq[4 * EDIM + e];
    }

    // kmeans_rgb = rgb_clusters[idx, cluster_id]  (3 rows of LM · enc)
    int cc = cids[idx];
    float km0 = 0.f, km1 = 0.f, km2 = 0.f;
    {
        const float* rp = sLM + (3 * cc) * EDIM;
#pragma unroll
        for (int e = 0; e < EDIM; e++) {
            float ev = enc[e];
            km0 += ev * rp[e];
            km1 += ev * rp[EDIM + e];
            km2 += ev * rp[2 * EDIM + e];
        }
    }

    // pack enc into f32x2 pairs
    unsigned long long encp[EDIM / 2];
#pragma unroll
    for (int i = 0; i < EDIM / 2; i++) PACK2(encp[i], enc[2 * i], enc[2 * i + 1]);

    // pass 1: running max of scores (scores recomputed in pass 2 — cheaper
    // than holding a 64-entry register array, keeps c-loop rolled)
    float m = -1e30f;
    for (int c = 0; c < NC; c++) {
        const float* kc = sK + c * DKDIM;
        float s = q0 * kc[0] + q1 * kc[1] + q2 * kc[2] + q3 * kc[3] + q4 * kc[4];
        s *= INV_SQRT5;
        m = fmaxf(m, s);
    }

    // pass 2: Z and unnormalized weighted accumulation of rgb over clusters
    float Z = 0.f;
    unsigned long long ga0 = 0, ga1 = 0, ga2 = 0, ga3 = 0, ga4 = 0, ga5 = 0;
    for (int c = 0; c < NC; c++) {
        const float* kc = sK + c * DKDIM;
        float s = q0 * kc[0] + q1 * kc[1] + q2 * kc[2] + q3 * kc[3] + q4 * kc[4];
        s *= INV_SQRT5;
        float w = __expf(s - m);
        Z += w;
        unsigned long long wp;
        PACK2(wp, w, w);

        unsigned long long r0 = 0, r1 = 0, r2 = 0, r3 = 0, r4 = 0, r5 = 0;
        // 3 consecutive LM rows (3c, 3c+1, 3c+2), 60 floats each = 15 float4s.
        // Row byte offset 3c*240 is 16B-aligned (240 = 15*16).
        const ulonglong2* row = (const ulonglong2*)(sLM + 3 * c * EDIM);
#pragma unroll
        for (int t = 0; t < 15; t++) {
            ulonglong2 a0 = row[t];           // j=0 : e = 4t..4t+3 (broadcast LDS.128)
            ulonglong2 a1 = row[15 + t];      // j=1
            ulonglong2 a2 = row[30 + t];      // j=2
            FMA2(r0, a0.x, encp[2 * t],     r0);
            FMA2(r1, a0.y, encp[2 * t + 1], r1);
            FMA2(r2, a1.x, encp[2 * t],     r2);
            FMA2(r3, a1.y, encp[2 * t + 1], r3);
            FMA2(r4, a2.x, encp[2 * t],     r4);
            FMA2(r5, a2.y, encp[2 * t + 1], r5);
        }
        FMA2(ga0, wp, r0, ga0);
        FMA2(ga1, wp, r1, ga1);
        FMA2(ga2, wp, r2, ga2);
        FMA2(ga3, wp, r3, ga3);
        FMA2(ga4, wp, r4, ga4);
        FMA2(ga5, wp, r5, ga5);
    }

    float invZ = 1.0f / Z;
    float t0, t1, t2;
    {
        float a, b;
        a = __uint_as_float((unsigned)ga0) + __uint_as_float((unsigned)(ga0 >> 32));
        b = __uint_as_float((unsigned)ga1) + __uint_as_float((unsigned)(ga1 >> 32));
        t0 = (a + b) * invZ;
        a = __uint_as_float((unsigned)ga2) + __uint_as_float((unsigned)(ga2 >> 32));
        b = __uint_as_float((unsigned)ga3) + __uint_as_float((unsigned)(ga3 >> 32));
        t1 = (a + b) * invZ;
        a = __uint_as_float((unsigned)ga4) + __uint_as_float((unsigned)(ga4 >> 32));
        b = __uint_as_float((unsigned)ga5) + __uint_as_float((unsigned)(ga5 >> 32));
        t2 = (a + b) * invZ;
    }

    // V = rgb @ Wv^T : attention_rgb_i = sum_j Wv[i,j] * t_j
    float at0 = sWv[0] * t0 + sWv[1] * t1 + sWv[2] * t2;
    float at1 = sWv[3] * t0 + sWv[4] * t1 + sWv[5] * t2;
    float at2 = sWv[6] * t0 + sWv[7] * t1 + sWv[8] * t2;

    const float TR = 1.0f;
    float o0 = km0 * TR + at0 * (1.0f - TR);
    float o1 = km1 * TR + at1 * (1.0f - TR);
    float o2 = km2 * TR + at2 * (1.0f - TR);

    d_out[3 * idx + 0] = o0;
    d_out[3 * idx + 1] = o1;
    d_out[3 * idx + 2] = o2;
    if (mode == 3) {
        float* kmp = d_out + 3 * (size_t)N;
        float* atp = d_out + 6 * (size_t)N;
        kmp[3 * idx + 0] = km0;
        kmp[3 * idx + 1] = km1;
        kmp[3 * idx + 2] = km2;
        atp[3 * idx + 0] = at0;
        atp[3 * idx + 1] = at1;
        atp[3 * idx + 2] = at2;
    }
}

extern "C" void kernel_launch(void* const* d_in, const int* in_sizes, int n_in,
                              void* d_out, int out_size) {
    const float* X         = (const float*)d_in[0];
    const int*   cids      = (const int*)  d_in[1];
    const float* LM        = (const float*)d_in[2];
    const float* Wq        = (const float*)d_in[3];
    const float* Wk        = (const float*)d_in[4];
    const float* Wv        = (const float*)d_in[5];
    const float* centroids = (const float*)d_in[6];

    int N = in_sizes[0] / 3;
    int mode = (out_size >= 9 * N) ? 3 : 1;

    precompute_K_kernel<<<1, 64>>>(Wk, centroids);
    int blocks = (N + TPB - 1) / TPB;
    csa_kernel<<<blocks, TPB>>>(X, cids, LM, Wq, Wv, (float*)d_out, N, mode);
}

// round 8
// speedup vs baseline: 1.0008x; 1.0008x over previous
#include <cuda_runtime.h>

#define TPB 256
#define NF 10
#define EDIM 60
#define NC 64
#define DKDIM 5
#define INV_SQRT5 0.44721359549995793f

// Packed f32x2 FMA — ptxas never auto-fuses this from C++; PTX-only (sm_100+).
#define FMA2(d, a, b, c) \
    asm("fma.rn.f32x2 %0, %1, %2, %3;" : "=l"(d) : "l"(a), "l"(b), "l"(c))
#define PACK2(d, lo, hi) \
    asm("mov.b64 %0, {%1, %2};" : "=l"(d) : "f"(lo), "f"(hi))

__device__ float g_K[NC * DKDIM];  // K = posenc(centroids) @ Wk^T, precomputed

// ---------------------------------------------------------------------------
// Tiny kernel: K[c, k] = sum_e posenc(centroid_c)[e] * Wk[k, e]
// ---------------------------------------------------------------------------
__global__ void precompute_K_kernel(const float* __restrict__ Wk,
                                    const float* __restrict__ centroids) {
    int c = threadIdx.x;
    if (c >= NC) return;
    float x0 = centroids[c * 3 + 0];
    float x1 = centroids[c * 3 + 1];
    float x2 = centroids[c * 3 + 2];
    float enc[EDIM];
#pragma unroll
    for (int l = 0; l < NF; l++) {
        float f = (float)(1u << l);
        float s, co;
        sincosf(x0 * f, &s, &co); enc[l * 6 + 0] = s; enc[l * 6 + 3] = co;
        sincosf(x1 * f, &s, &co); enc[l * 6 + 1] = s; enc[l * 6 + 4] = co;
        sincosf(x2 * f, &s, &co); enc[l * 6 + 2] = s; enc[l * 6 + 5] = co;
    }
#pragma unroll
    for (int k = 0; k < DKDIM; k++) {
        float a = 0.f;
#pragma unroll
        for (int e = 0; e < EDIM; e++) a += enc[e] * Wk[k * EDIM + e];
        g_K[c * DKDIM + k] = a;
    }
}

// ---------------------------------------------------------------------------
// Main kernel: one thread per point.
//   enc (60) in regs; LM (192x60 = 46 KB) in smem, broadcast-read;
//   softmax fused unnormalized (divide by Z at the end) so the c-loop stays
//   rolled and no 64-entry register array is needed;
//   inner reduction uses packed fma.rn.f32x2 (2 FMAs/lane/instr).
// ---------------------------------------------------------------------------
__global__ __launch_bounds__(TPB) void csa_kernel(
    const float* __restrict__ X,
    const int*   __restrict__ cids,
    const float* __restrict__ LM,
    const float* __restrict__ Wq,
    const float* __restrict__ Wv,
    float* __restrict__ d_out,
    int N, int mode)   // mode 3: write [out | kmeans | attention]; mode 1: out only
{
    __shared__ __align__(16) float sLM[192 * EDIM];   // 46080 B
    __shared__ float sK[NC * DKDIM];
    __shared__ float sWq[DKDIM * EDIM];
    __shared__ float sWv[9];

    {
        const float4* src = (const float4*)LM;
        float4* dst = (float4*)sLM;
        for (int i = threadIdx.x; i < 192 * EDIM / 4; i += TPB) dst[i] = src[i];
        for (int i = threadIdx.x; i < NC * DKDIM; i += TPB) sK[i] = g_K[i];
        for (int i = threadIdx.x; i < DKDIM * EDIM; i += TPB) sWq[i] = Wq[i];
        if (threadIdx.x < 9) sWv[threadIdx.x] = Wv[threadIdx.x];
    }
    __syncthreads();

    int idx = blockIdx.x * TPB + threadIdx.x;
    if (idx >= N) return;

    float x0 = X[3 * idx + 0];
    float x1 = X[3 * idx + 1];
    float x2 = X[3 * idx + 2];

    // NeRF posenc: enc[l*6 + s*3 + d], s=0 sin, s=1 cos
    float enc[EDIM];
#pragma unroll
    for (int l = 0; l < NF; l++) {
        float f = (float)(1u << l);
        float s, co;
        sincosf(x0 * f, &s, &co); enc[l * 6 + 0] = s; enc[l * 6 + 3] = co;
        sincosf(x1 * f, &s, &co); enc[l * 6 + 1] = s; enc[l * 6 + 4] = co;
        sincosf(x2 * f, &s, &co); enc[l * 6 + 2] = s; enc[l * 6 + 5] = co;
    }

    // Q = enc @ Wq^T   [5]
    float q0 = 0.f, q1 = 0.f, q2 = 0.f, q3 = 0.f, q4 = 0.f;
#pragma unroll
    for (int e = 0; e < EDIM; e++) {
        float ev = enc[e];
        q0 += ev * sWq[0 * EDIM + e];
        q1 += ev * sWq[1 * EDIM + e];
        q2 += ev * sWq[2 * EDIM + e];
        q3 += ev * sWq[3 * EDIM + e];
        q4 += ev * sWq[4 * EDIM + e];
    }

    // kmeans_rgb = rgb_clusters[idx, cluster_id]  (3 rows of LM · enc)
    int cc = cids[idx];
    float km0 = 0.f, km1 = 0.f, km2 = 0.f;
    {
        const float* rp = sLM + (3 * cc) * EDIM;
#pragma unroll
        for (int e = 0; e < EDIM; e++) {
            float ev = enc[e];
            km0 += ev * rp[e];
            km1 += ev * rp[EDIM + e];
            km2 += ev * rp[2 * EDIM + e];
        }
    }

    // pack enc into f32x2 pairs
    unsigned long long encp[EDIM / 2];
#pragma unroll
    for (int i = 0; i < EDIM / 2; i++) PACK2(encp[i], enc[2 * i], enc[2 * i + 1]);

    // pass 1: running max of scores (scores recomputed in pass 2 — cheaper
    // than holding a 64-entry register array, keeps c-loop rolled)
    float m = -1e30f;
    for (int c = 0; c < NC; c++) {
        const float* kc = sK + c * DKDIM;
        float s = q0 * kc[0] + q1 * kc[1] + q2 * kc[2] + q3 * kc[3] + q4 * kc[4];
        s *= INV_SQRT5;
        m = fmaxf(m, s);
    }

    // pass 2: Z and unnormalized weighted accumulation of rgb over clusters
    float Z = 0.f;
    unsigned long long ga0 = 0, ga1 = 0, ga2 = 0, ga3 = 0, ga4 = 0, ga5 = 0;
    for (int c = 0; c < NC; c++) {
        const float* kc = sK + c * DKDIM;
        float s = q0 * kc[0] + q1 * kc[1] + q2 * kc[2] + q3 * kc[3] + q4 * kc[4];
        s *= INV_SQRT5;
        float w = __expf(s - m);
        Z += w;
        unsigned long long wp;
        PACK2(wp, w, w);

        unsigned long long r0 = 0, r1 = 0, r2 = 0, r3 = 0, r4 = 0, r5 = 0;
        // 3 consecutive LM rows (3c, 3c+1, 3c+2), 60 floats each = 15 float4s.
        // Row byte offset 3c*240 is 16B-aligned (240 = 15*16).
        const ulonglong2* row = (const ulonglong2*)(sLM + 3 * c * EDIM);
#pragma unroll
        for (int t = 0; t < 15; t++) {
            ulonglong2 a0 = row[t];           // j=0 : e = 4t..4t+3 (broadcast LDS.128)
            ulonglong2 a1 = row[15 + t];      // j=1
            ulonglong2 a2 = row[30 + t];      // j=2
            FMA2(r0, a0.x, encp[2 * t],     r0);
            FMA2(r1, a0.y, encp[2 * t + 1], r1);
            FMA2(r2, a1.x, encp[2 * t],     r2);
            FMA2(r3, a1.y, encp[2 * t + 1], r3);
            FMA2(r4, a2.x, encp[2 * t],     r4);
            FMA2(r5, a2.y, encp[2 * t + 1], r5);
        }
        FMA2(ga0, wp, r0, ga0);
        FMA2(ga1, wp, r1, ga1);
        FMA2(ga2, wp, r2, ga2);
        FMA2(ga3, wp, r3, ga3);
        FMA2(ga4, wp, r4, ga4);
        FMA2(ga5, wp, r5, ga5);
    }

    float invZ = 1.0f / Z;
    float t0, t1, t2;
    {
        float a, b;
        a = __uint_as_float((unsigned)ga0) + __uint_as_float((unsigned)(ga0 >> 32));
        b = __uint_as_float((unsigned)ga1) + __uint_as_float((unsigned)(ga1 >> 32));
        t0 = (a + b) * invZ;
        a = __uint_as_float((unsigned)ga2) + __uint_as_float((unsigned)(ga2 >> 32));
        b = __uint_as_float((unsigned)ga3) + __uint_as_float((unsigned)(ga3 >> 32));
        t1 = (a + b) * invZ;
        a = __uint_as_float((unsigned)ga4) + __uint_as_float((unsigned)(ga4 >> 32));
        b = __uint_as_float((unsigned)ga5) + __uint_as_float((unsigned)(ga5 >> 32));
        t2 = (a + b) * invZ;
    }

    // V = rgb @ Wv^T : attention_rgb_i = sum_j Wv[i,j] * t_j
    float at0 = sWv[0] * t0 + sWv[1] * t1 + sWv[2] * t2;
    float at1 = sWv[3] * t0 + sWv[4] * t1 + sWv[5] * t2;
    float at2 = sWv[6] * t0 + sWv[7] * t1 + sWv[8] * t2;

    const float TR = 1.0f;
    float o0 = km0 * TR + at0 * (1.0f - TR);
    float o1 = km1 * TR + at1 * (1.0f - TR);
    float o2 = km2 * TR + at2 * (1.0f - TR);

    d_out[3 * idx + 0] = o0;
    d_out[3 * idx + 1] = o1;
    d_out[3 * idx + 2] = o2;
    if (mode == 3) {
        float* kmp = d_out + 3 * (size_t)N;
        float* atp = d_out + 6 * (size_t)N;
        kmp[3 * idx + 0] = km0;
        kmp[3 * idx + 1] = km1;
        kmp[3 * idx + 2] = km2;
        atp[3 * idx + 0] = at0;
        atp[3 * idx + 1] = at1;
        atp[3 * idx + 2] = at2;
    }
}

extern "C" void kernel_launch(void* const* d_in, const int* in_sizes, int n_in,
                              void* d_out, int out_size) {
    const float* X         = (const float*)d_in[0];
    const int*   cids      = (const int*)  d_in[1];
    const float* LM        = (const float*)d_in[2];
    const float* Wq        = (const float*)d_in[3];
    const float* Wk        = (const float*)d_in[4];
    const float* Wv        = (const float*)d_in[5];
    const float* centroids = (const float*)d_in[6];

    int N = in_sizes[0] / 3;
    int mode = (out_size >= 9 * N) ? 3 : 1;

    precompute_K_kernel<<<1, 64>>>(Wk, centroids);
    int blocks = (N + TPB - 1) / TPB;
    csa_kernel<<<blocks, TPB>>>(X, cids, LM, Wq, Wv, (float*)d_out, N, mode);
}

// round 9
// speedup vs baseline: 1.2691x; 1.2682x over previous
#include <cuda_runtime.h>

#define TPB 128
#define NF 10
#define EDIM 60
#define NC 64
#define DKDIM 5
#define INV_SQRT5 0.44721359549995793f

// Packed f32x2 FMA — PTX-only; ptxas never auto-fuses from C++ (sm_100+).
#define FMA2(d, a, b, c) \
    asm("fma.rn.f32x2 %0, %1, %2, %3;" : "=l"(d) : "l"(a), "l"(b), "l"(c))
#define PACK2(d, lo, hi) \
    asm("mov.b64 %0, {%1, %2};" : "=l"(d) : "f"(lo), "f"(hi))

__device__ float g_K[NC * 8];  // K = posenc(centroids) @ Wk^T, padded stride 8

// ---------------------------------------------------------------------------
__global__ void precompute_K_kernel(const float* __restrict__ Wk,
                                    const float* __restrict__ centroids) {
    int c = threadIdx.x;
    if (c >= NC) return;
    float x0 = centroids[c * 3 + 0];
    float x1 = centroids[c * 3 + 1];
    float x2 = centroids[c * 3 + 2];
    float enc[EDIM];
#pragma unroll
    for (int l = 0; l < NF; l++) {
        float f = (float)(1u << l);
        float s, co;
        sincosf(x0 * f, &s, &co); enc[l * 6 + 0] = s; enc[l * 6 + 3] = co;
        sincosf(x1 * f, &s, &co); enc[l * 6 + 1] = s; enc[l * 6 + 4] = co;
        sincosf(x2 * f, &s, &co); enc[l * 6 + 2] = s; enc[l * 6 + 5] = co;
    }
#pragma unroll
    for (int k = 0; k < 8; k++) {
        float a = 0.f;
        if (k < DKDIM) {
#pragma unroll
            for (int e = 0; e < EDIM; e++) a += enc[e] * Wk[k * EDIM + e];
        }
        g_K[c * 8 + k] = a;
    }
}

// ---------------------------------------------------------------------------
__device__ __forceinline__ float hsum2(unsigned long long v) {
    return __uint_as_float((unsigned)v) + __uint_as_float((unsigned)(v >> 32));
}

// Per-point preamble: posenc, Q (pre-scaled by 1/sqrt(5)), kmeans gather,
// packed enc pairs.
__device__ __forceinline__ void prep_point(
    const float* __restrict__ X, const int* __restrict__ cids,
    const float* sLM, const float* sWq, int idx,
    float* q, float* km, unsigned long long* encp)
{
    float x0 = X[3 * idx + 0];
    float x1 = X[3 * idx + 1];
    float x2 = X[3 * idx + 2];
    float enc[EDIM];
#pragma unroll
    for (int l = 0; l < NF; l++) {
        float f = (float)(1u << l);
        float s, co;
        sincosf(x0 * f, &s, &co); enc[l * 6 + 0] = s; enc[l * 6 + 3] = co;
        sincosf(x1 * f, &s, &co); enc[l * 6 + 1] = s; enc[l * 6 + 4] = co;
        sincosf(x2 * f, &s, &co); enc[l * 6 + 2] = s; enc[l * 6 + 5] = co;
    }
#pragma unroll
    for (int k = 0; k < DKDIM; k++) {
        float a = 0.f;
#pragma unroll
        for (int e = 0; e < EDIM; e++) a += enc[e] * sWq[k * EDIM + e];
        q[k] = a * INV_SQRT5;   // fold score scaling into Q
    }
    // kmeans_rgb: 3 LM rows of own cluster, vectorized LDS.128
    int cc = cids[idx];
    const float4* rp = (const float4*)(sLM + 3 * cc * EDIM);
    float k0 = 0.f, k1 = 0.f, k2 = 0.f;
#pragma unroll
    for (int t = 0; t < 15; t++) {
        float4 a = rp[t], b = rp[15 + t], c4 = rp[30 + t];
        float e0 = enc[4 * t], e1 = enc[4 * t + 1];
        float e2 = enc[4 * t + 2], e3 = enc[4 * t + 3];
        k0 += a.x  * e0 + a.y  * e1 + a.z  * e2 + a.w  * e3;
        k1 += b.x  * e0 + b.y  * e1 + b.z  * e2 + b.w  * e3;
        k2 += c4.x * e0 + c4.y * e1 + c4.z * e2 + c4.w * e3;
    }
    km[0] = k0; km[1] = k1; km[2] = k2;
#pragma unroll
    for (int i = 0; i < EDIM / 2; i++) PACK2(encp[i], enc[2 * i], enc[2 * i + 1]);
}

__device__ __forceinline__ void store_point(
    float* __restrict__ d_out, const float* sWv, int idx, int N, int mode,
    const float* km, const unsigned long long* g, float Z)
{
    float invZ = 1.0f / Z;
    float t0 = (hsum2(g[0]) + hsum2(g[1])) * invZ;
    float t1 = (hsum2(g[2]) + hsum2(g[3])) * invZ;
    float t2 = (hsum2(g[4]) + hsum2(g[5])) * invZ;
    float at0 = sWv[0] * t0 + sWv[1] * t1 + sWv[2] * t2;
    float at1 = sWv[3] * t0 + sWv[4] * t1 + sWv[5] * t2;
    float at2 = sWv[6] * t0 + sWv[7] * t1 + sWv[8] * t2;
    const float TR = 1.0f;
    d_out[3 * idx + 0] = km[0] * TR + at0 * (1.0f - TR);
    d_out[3 * idx + 1] = km[1] * TR + at1 * (1.0f - TR);
    d_out[3 * idx + 2] = km[2] * TR + at2 * (1.0f - TR);
    if (mode == 3) {
        float* kmp = d_out + 3 * (size_t)N;
        float* atp = d_out + 6 * (size_t)N;
        kmp[3 * idx + 0] = km[0];
        kmp[3 * idx + 1] = km[1];
        kmp[3 * idx + 2] = km[2];
        atp[3 * idx + 0] = at0;
        atp[3 * idx + 1] = at1;
        atp[3 * idx + 2] = at2;
    }
}

// ---------------------------------------------------------------------------
// Main kernel: TWO points per thread. LM broadcast loads amortized 2x;
// softmax unnormalized (no max pass — scores are O(1), exp can't overflow);
// all heavy math in packed fma.rn.f32x2.
// ---------------------------------------------------------------------------
__global__ __launch_bounds__(TPB, 1) void csa_kernel(
    const float* __restrict__ X,
    const int*   __restrict__ cids,
    const float* __restrict__ LM,
    const float* __restrict__ Wq,
    const float* __restrict__ Wv,
    float* __restrict__ d_out,
    int N, int mode)
{
    __shared__ __align__(16) float sLM[192 * EDIM];   // 46080 B
    __shared__ __align__(16) float sK[NC * 8];
    __shared__ float sWq[DKDIM * EDIM];
    __shared__ float sWv[9];

    for (int i = threadIdx.x; i < 192 * EDIM / 4; i += TPB)
        ((float4*)sLM)[i] = ((const float4*)LM)[i];
    for (int i = threadIdx.x; i < NC * 8; i += TPB) sK[i] = g_K[i];
    for (int i = threadIdx.x; i < DKDIM * EDIM; i += TPB) sWq[i] = Wq[i];
    if (threadIdx.x < 9) sWv[threadIdx.x] = Wv[threadIdx.x];
    __syncthreads();

    int base = blockIdx.x * (TPB * 2) + threadIdx.x;
    int iA = base;
    int iB = base + TPB;
    bool vA = iA < N, vB = iB < N;
    int pA = min(iA, N - 1), pB = min(iB, N - 1);

    float qA[DKDIM], qB[DKDIM];
    float kmA[3], kmB[3];
    unsigned long long encA[EDIM / 2], encB[EDIM / 2];

    prep_point(X, cids, sLM, sWq, pA, qA, kmA, encA);
    prep_point(X, cids, sLM, sWq, pB, qB, kmB, encB);

    float ZA = 0.f, ZB = 0.f;
    unsigned long long gA[6] = {0, 0, 0, 0, 0, 0};
    unsigned long long gB[6] = {0, 0, 0, 0, 0, 0};

    for (int c = 0; c < NC; c++) {
        // scores (K broadcast, stride-8 padded: one LDS.128 + one LDS.32)
        float4 kl = ((const float4*)(sK + c * 8))[0];
        float  k4 = sK[c * 8 + 4];
        float sA = qA[0] * kl.x + qA[1] * kl.y + qA[2] * kl.z + qA[3] * kl.w + qA[4] * k4;
        float sB = qB[0] * kl.x + qB[1] * kl.y + qB[2] * kl.z + qB[3] * kl.w + qB[4] * k4;
        float wA = __expf(sA), wB = __expf(sB);
        ZA += wA; ZB += wB;
        unsigned long long wpA, wpB;
        PACK2(wpA, wA, wA);
        PACK2(wpB, wB, wB);

        unsigned long long rA0 = 0, rA1 = 0, rA2 = 0, rA3 = 0, rA4 = 0, rA5 = 0;
        unsigned long long rB0 = 0, rB1 = 0, rB2 = 0, rB3 = 0, rB4 = 0, rB5 = 0;
        // 3 consecutive LM rows (3c..3c+2), 60 floats each = 15 float4 per row.
        const ulonglong2* row = (const ulonglong2*)(sLM + 3 * c * EDIM);
#pragma unroll
        for (int t = 0; t < 15; t++) {
            ulonglong2 a0 = row[t];        // broadcast LDS.128 — 1 wavefront
            ulonglong2 a1 = row[15 + t];
            ulonglong2 a2 = row[30 + t];
            unsigned long long e0 = encA[2 * t], e1 = encA[2 * t + 1];
            FMA2(rA0, a0.x, e0, rA0); FMA2(rA1, a0.y, e1, rA1);
            FMA2(rA2, a1.x, e0, rA2); FMA2(rA3, a1.y, e1, rA3);
            FMA2(rA4, a2.x, e0, rA4); FMA2(rA5, a2.y, e1, rA5);
            e0 = encB[2 * t]; e1 = encB[2 * t + 1];
            FMA2(rB0, a0.x, e0, rB0); FMA2(rB1, a0.y, e1, rB1);
            FMA2(rB2, a1.x, e0, rB2); FMA2(rB3, a1.y, e1, rB3);
            FMA2(rB4, a2.x, e0, rB4); FMA2(rB5, a2.y, e1, rB5);
        }
        FMA2(gA[0], wpA, rA0, gA[0]); FMA2(gA[1], wpA, rA1, gA[1]);
        FMA2(gA[2], wpA, rA2, gA[2]); FMA2(gA[3], wpA, rA3, gA[3]);
        FMA2(gA[4], wpA, rA4, gA[4]); FMA2(gA[5], wpA, rA5, gA[5]);
        FMA2(gB[0], wpB, rB0, gB[0]); FMA2(gB[1], wpB, rB1, gB[1]);
        FMA2(gB[2], wpB, rB2, gB[2]); FMA2(gB[3], wpB, rB3, gB[3]);
        FMA2(gB[4], wpB, rB4, gB[4]); FMA2(gB[5], wpB, rB5, gB[5]);
    }

    if (vA) store_point(d_out, sWv, iA, N, mode, kmA, gA, ZA);
    if (vB) store_point(d_out, sWv, iB, N, mode, kmB, gB, ZB);
}

extern "C" void kernel_launch(void* const* d_in, const int* in_sizes, int n_in,
                              void* d_out, int out_size) {
    const float* X         = (const float*)d_in[0];
    const int*   cids      = (const int*)  d_in[1];
    const float* LM        = (const float*)d_in[2];
    const float* Wq        = (const float*)d_in[3];
    const float* Wk        = (const float*)d_in[4];
    const float* Wv        = (const float*)d_in[5];
    const float* centroids = (const float*)d_in[6];

    int N = in_sizes[0] / 3;
    int mode = (out_size >= 9 * N) ? 3 : 1;

    precompute_K_kernel<<<1, 64>>>(Wk, centroids);
    int blocks = (N + TPB * 2 - 1) / (TPB * 2);
    csa_kernel<<<blocks, TPB>>>(X, cids, LM, Wq, Wv, (float*)d_out, N, mode);
}